// round 11
// baseline (speedup 1.0000x reference)
#include <cuda_runtime.h>
#include <cuda_fp16.h>
#include <math.h>
#include <stdint.h>

#define BATCH 512
#define SEQ   256
#define D     64
#define H     512
#define G     2048
#define KDIM  576
#define PRED  24

#define NCTA  128
#define NTHR  512

// ---- smem layout (bytes). B first, then A region. ----
#define SWW    296                            /* words per A/B row (288 data + 8 pad) */
#define SM_B   0
#define SM_B_BYTES (64 * SWW * 4)             /* 75776  */
#define SM_A   SM_B_BYTES
#define SM_A_BYTES (128 * SWW * 4)            /* 151552 */
#define SMEM_TOTAL (SM_A + SM_A_BYTES)        /* 227328 */

// attn scratch offsets inside A region (phases barrier-separated from A use)
#define AT_HC   0                             /* 4 x 1024 f32 = 16384 */
#define AT_PART 16384                         /* 2 x 4 x 64 f32 = 2048 */
#define AT_PRE  18432                         /* 4 x 64 f32 = 1024 */
#define AT_WRED 19456                         /* 16 f32 */
#define AT_UB   20480                         /* 4 x 16384 Ua chunk buffers */

// ---------------- device scratch ----------------
__device__ __half g_W16[KDIM * G];   // fp16 weights, [k][g'], g' = hh*4 + t
__device__ float g_bias[G];
__device__ float g_h[2][BATCH * H];
__device__ float g_c[2][BATCH * H];
__device__ float g_xatt[BATCH * D];
__device__ float g_xw[SEQ * BATCH * D];

// per-group (32-CTA) barriers, padded to separate cache lines
__device__ unsigned g_gb_cnt[4][32];
__device__ volatile unsigned g_gb_gen[4][32];

__device__ __forceinline__ float sigf(float x) { return 1.0f / (1.0f + expf(-x)); }

// k-interleave: pair index pc (k/2) -> word within row
__device__ __forceinline__ int kword(int pc) {
    int grp = pc >> 3, cg = pc & 7;
    return grp * 8 + (cg & 3) * 2 + (cg >> 2);
}

__device__ __forceinline__ void mma_fp16(float* d, uint32_t a0, uint32_t a1,
                                         uint32_t a2, uint32_t a3,
                                         uint32_t b0, uint32_t b1) {
    asm volatile(
        "mma.sync.aligned.m16n8k16.row.col.f32.f16.f16.f32 "
        "{%0,%1,%2,%3}, {%4,%5,%6,%7}, {%8,%9}, {%0,%1,%2,%3};"
        : "+f"(d[0]), "+f"(d[1]), "+f"(d[2]), "+f"(d[3])
        : "r"(a0), "r"(a1), "r"(a2), "r"(a3), "r"(b0), "r"(b1));
}

__device__ __forceinline__ void barhalf(int id) {
    asm volatile("bar.sync %0, 256;" :: "r"(id) : "memory");
}

// 32-CTA group barrier (group = blockIdx.x >> 5); all 32 CTAs co-resident.
__device__ __forceinline__ void group_barrier(int grp) {
    __syncthreads();
    if (threadIdx.x == 0) {
        __threadfence();
        unsigned gen = g_gb_gen[grp][0];
        if (atomicAdd(&g_gb_cnt[grp][0], 1u) == 31u) {
            g_gb_cnt[grp][0] = 0;
            __threadfence();
            g_gb_gen[grp][0] = gen + 1;
        } else {
            while (g_gb_gen[grp][0] == gen) { }
        }
        __threadfence();
    }
    __syncthreads();
}

// ---------------- init: permute+convert weights, zero state ----------------
__global__ void __launch_bounds__(256) init_kernel(const float* __restrict__ W_ih,
                                                   const float* __restrict__ W_hh,
                                                   const float* __restrict__ b_ih,
                                                   const float* __restrict__ b_hh) {
    const int stride = gridDim.x * blockDim.x;
    const int tid0 = blockIdx.x * blockDim.x + threadIdx.x;
    for (int idx = tid0; idx < KDIM * G; idx += stride) {
        int k = idx / G, gp = idx - k * G;
        int hh = gp >> 2, t = gp & 3, g = t * H + hh;
        float v = (k < D) ? W_ih[g * D + k] : W_hh[g * H + (k - D)];
        g_W16[idx] = __float2half_rn(v);
    }
    for (int idx = tid0; idx < G; idx += stride) {
        int hh = idx >> 2, t = idx & 3, g = t * H + hh;
        g_bias[idx] = b_ih[g] + b_hh[g];
    }
    for (int idx = tid0; idx < BATCH * H; idx += stride) {
        g_h[0][idx] = 0.0f;
        g_c[0][idx] = 0.0f;
    }
}

// ---------------- one-time xw = x@Wa + ba ----------------
__global__ void __launch_bounds__(256) xw_kernel(const float* __restrict__ x,
                                                 const float* __restrict__ Wa,
                                                 const float* __restrict__ ba) {
    __shared__ float Wa_s[D * D];
    __shared__ float xs[32][D];
    const int tid = threadIdx.x;
    const int r0 = blockIdx.x * 32;
    const int s = r0 / BATCH, b0 = r0 % BATCH;
    {
        const float4* src = (const float4*)Wa; float4* dst = (float4*)Wa_s;
#pragma unroll
        for (int j = 0; j < 4; j++) dst[tid + j * 256] = src[tid + j * 256];
    }
#pragma unroll
    for (int j = 0; j < 8; j++) {
        int idx = tid + j * 256; int i = idx >> 6, dd = idx & 63;
        xs[i][dd] = x[((b0 + i) * SEQ + s) * D + dd];
    }
    __syncthreads();
    const int d = tid & 63, grp = tid >> 6;
    float bv = ba[d], acc[8];
#pragma unroll
    for (int i = 0; i < 8; i++) acc[i] = bv;
#pragma unroll
    for (int k = 0; k < D; k += 4) {
        float w0 = Wa_s[k * D + d], w1 = Wa_s[(k + 1) * D + d];
        float w2 = Wa_s[(k + 2) * D + d], w3 = Wa_s[(k + 3) * D + d];
#pragma unroll
        for (int i = 0; i < 8; i++) {
            float4 xv = *(const float4*)&xs[grp * 8 + i][k];
            acc[i] = fmaf(xv.x, w0, acc[i]); acc[i] = fmaf(xv.y, w1, acc[i]);
            acc[i] = fmaf(xv.z, w2, acc[i]); acc[i] = fmaf(xv.w, w3, acc[i]);
        }
    }
#pragma unroll
    for (int i = 0; i < 8; i++) g_xw[(r0 + grp * 8 + i) * D + d] = acc[i];
}

// ---------------- persistent kernel ----------------
__global__ void __launch_bounds__(NTHR, 1)
persist_kernel(const float* __restrict__ x, const float* __restrict__ Ua,
               const float* __restrict__ Va) {
    extern __shared__ __align__(16) char smem[];
    const int tid = threadIdx.x;
    const int cta = blockIdx.x;
    const int ct = cta & 31, bt = cta >> 5;
    const int colbase = ct * 64, bbase = bt * 128;
    const int lane = tid & 31, wid = tid >> 5;

    // ---- load fp16 weight slice into interleaved B smem (once) ----
    {
        __half* Bh = (__half*)(smem + SM_B);
        for (int idx = tid; idx < 64 * KDIM; idx += NTHR) {
            int k = idx >> 6, n = idx & 63;
            __half w = g_W16[k * G + colbase + n];
            Bh[n * (SWW * 2) + kword(k >> 1) * 2 + (k & 1)] = w;
        }
    }

    // attn scratch views
    float (*hc_s)[2 * H] = (float (*)[2 * H])(smem + SM_A + AT_HC);
    float (*part_s)[4][D] = (float (*)[4][D])(smem + SM_A + AT_PART);
    float* pre_s = (float*)(smem + SM_A + AT_PRE);
    float* wred  = (float*)(smem + SM_A + AT_WRED);
    float* wred2 = wred + 8;
    float* Cs    = (float*)(smem + SM_A);     // epilogue scratch 128x68

    // attn mapping: half (0: h-part k 0..511, 1: c-part), 256 threads each = 4 rows x 64 d
    const int half = tid >> 8;
    const int t256 = tid & 255;
    const int arow = t256 >> 6, ad = t256 & 63, ab = cta * 4 + arow;
    float* Ub[2];   // this half's double buffers
    Ub[0] = (float*)(smem + SM_A + AT_UB + (half * 2 + 0) * 16384);
    Ub[1] = (float*)(smem + SM_A + AT_UB + (half * 2 + 1) * 16384);
    float* Va_s = (float*)(smem + SM_A + AT_UB);   // reuse buffer 0 of half 0

    // mma mapping: warps 0..7, [32 rows x 32 cols] each
    const int mbase = (wid & 3) * 32;
    const int nbase = ((wid >> 2) & 1) * 32;
    const int fr = lane >> 2;
    const int fc = (lane & 3) * 2;

    // cell-update mapping: 512 threads x (4 rows x 1 quadruple)
    const int hhi   = tid & 15;
    const int rb4   = (tid >> 4) * 4;
    const int hh    = (colbase >> 2) + hhi;

    int pp = 0;
    group_barrier(bt);   // B smem staged; also initial sync

    for (int s = 0; s < SEQ; s++) {
        const float* __restrict__ h_in = g_h[pp];
        const float* __restrict__ c_in = g_c[pp];
        float* __restrict__ h_out = g_h[1 - pp];
        float* __restrict__ c_out = g_c[1 - pp];

        // ===================== attn phase =====================
        {
            // hc load by all 512 threads (h in [0,512), c in [512,1024))
#pragma unroll
            for (int j = 0; j < 8; j++) {
                int idx = tid + j * 512;
                int r = idx >> 10, k = idx & 1023;
                int bb = cta * 4 + r;
                hc_s[r][k] = (k < H) ? h_in[bb * H + k] : c_in[bb * H + (k - H)];
            }

            const int cbase = half * 512;     // this half's k-offset in hc / Ua rows
            // prologue: chunk 0 -> regs
            float4 pv[4];
            {
                const float4* src = (const float4*)(Ua + cbase * D);
#pragma unroll
                for (int j = 0; j < 4; j++) pv[j] = src[t256 + j * 256];
            }
            __syncthreads();                  // hc_s ready
            {
                float4* dst = (float4*)Ub[0];
#pragma unroll
                for (int j = 0; j < 4; j++) dst[t256 + j * 256] = pv[j];
            }
            barhalf(1 + half);

            float a0 = 0.0f, a1 = 0.0f, a2 = 0.0f, a3 = 0.0f;
            for (int ci = 0; ci < 8; ci++) {
                if (ci < 7) {
                    const float4* src = (const float4*)(Ua + (cbase + (ci + 1) * 64) * D);
#pragma unroll
                    for (int j = 0; j < 4; j++) pv[j] = src[t256 + j * 256];
                }
                const float* U = Ub[ci & 1];
                const int hb = cbase + ci * 64;
#pragma unroll
                for (int k = 0; k < 64; k += 4) {
                    float4 hv = *(const float4*)&hc_s[arow][hb + k];
                    a0 = fmaf(hv.x, U[(k + 0) * D + ad], a0);
                    a1 = fmaf(hv.y, U[(k + 1) * D + ad], a1);
                    a2 = fmaf(hv.z, U[(k + 2) * D + ad], a2);
                    a3 = fmaf(hv.w, U[(k + 3) * D + ad], a3);
                }
                if (ci < 7) {
                    float4* dst = (float4*)Ub[(ci + 1) & 1];
#pragma unroll
                    for (int j = 0; j < 4; j++) dst[t256 + j * 256] = pv[j];
                }
                barhalf(1 + half);
            }
            part_s[half][arow][ad] = (a0 + a1) + (a2 + a3);
            __syncthreads();   // both halves done; Ub[0][0] free

            // combine (warps 0-7) while Va staged (warps 8-15)
            if (half == 0) {
                float sum = part_s[0][arow][ad] + part_s[1][arow][ad] +
                            g_xw[(s * BATCH + ab) * D + ad];
                pre_s[arow * D + ad] = tanhf(sum);
            } else {
                const float4* src = (const float4*)Va;
                float4* dst = (float4*)Va_s;
#pragma unroll
                for (int j = 0; j < 4; j++) dst[t256 + j * 256] = src[t256 + j * 256];
            }
            __syncthreads();

            if (half == 0) {
                float v0 = 0.0f, v1 = 0.0f, v2 = 0.0f, v3 = 0.0f;
#pragma unroll
                for (int k = 0; k < D; k += 4) {
                    float4 pr = *(const float4*)&pre_s[arow * D + k];
                    v0 = fmaf(pr.x, Va_s[(k + 0) * D + ad], v0);
                    v1 = fmaf(pr.y, Va_s[(k + 1) * D + ad], v1);
                    v2 = fmaf(pr.z, Va_s[(k + 2) * D + ad], v2);
                    v3 = fmaf(pr.w, Va_s[(k + 3) * D + ad], v3);
                }
                float av = (v0 + v1) + (v2 + v3);

                float m = av;
#pragma unroll
                for (int off = 16; off > 0; off >>= 1)
                    m = fmaxf(m, __shfl_xor_sync(0xffffffffu, m, off));
                if (lane == 0) wred[wid] = m;
                barhalf(1);
                m = fmaxf(wred[arow * 2], wred[arow * 2 + 1]);

                float e = expf(av - m);
                float ssum = e;
#pragma unroll
                for (int off = 16; off > 0; off >>= 1)
                    ssum += __shfl_xor_sync(0xffffffffu, ssum, off);
                if (lane == 0) wred2[wid] = ssum;
                barhalf(1);
                ssum = wred2[arow * 2] + wred2[arow * 2 + 1];

                float xv = x[(ab * SEQ + s) * D + ad];
                g_xatt[ab * D + ad] = (e / ssum) * xv;
            }
        }

        group_barrier(bt);   // xatt visible within group

        // ========== gates: staged/pipelined A + mma (warps 0-7 mma, 8-15 stage) ==========
        float acc[2][4][4];
#pragma unroll
        for (int mt = 0; mt < 2; mt++)
#pragma unroll
            for (int j = 0; j < 4; j++)
#pragma unroll
                for (int q = 0; q < 4; q++) acc[mt][j][q] = 0.0f;

        {
            uint32_t* Aw = (uint32_t*)(smem + SM_A);
            const uint32_t* Bw = (const uint32_t*)(smem + SM_B);

            // stage one 144-k section: 128 rows x 36 float4
            auto stage = [&](int sec) {
                const int t2 = tid & 255;
#pragma unroll 2
                for (int j = 0; j < 18; j++) {
                    int idx = t2 + j * 256;
                    int row = idx / 36;
                    int kq  = idx - row * 36;
                    int k   = sec * 144 + kq * 4;
                    float4 v = (k < D)
                        ? *(const float4*)&g_xatt[(bbase + row) * D + k]
                        : *(const float4*)&h_in[(bbase + row) * H + (k - D)];
                    __half2 p0 = __floats2half2_rn(v.x, v.y);
                    __half2 p1 = __floats2half2_rn(v.z, v.w);
                    int kqg = k >> 2;
                    uint32_t* Ar = Aw + row * SWW;
                    Ar[kword(2 * kqg)]     = *(uint32_t*)&p0;
                    Ar[kword(2 * kqg + 1)] = *(uint32_t*)&p1;
                }
            };

            if (wid >= 8) stage(0);
            __syncthreads();

            for (int sec = 0; sec < 4; sec++) {
                if (wid < 8) {
#pragma unroll
                    for (int ki = 0; ki < 9; ki++) {
                        const int kw = (sec * 9 + ki) * 8 + fc;
                        uint2 fa0 = *(const uint2*)&Aw[(mbase + fr) * SWW + kw];
                        uint2 fa1 = *(const uint2*)&Aw[(mbase + fr + 8) * SWW + kw];
                        uint2 fa2 = *(const uint2*)&Aw[(mbase + 16 + fr) * SWW + kw];
                        uint2 fa3 = *(const uint2*)&Aw[(mbase + 24 + fr) * SWW + kw];
#pragma unroll
                        for (int j = 0; j < 4; j++) {
                            uint2 fb = *(const uint2*)&Bw[(nbase + j * 8 + fr) * SWW + kw];
                            mma_fp16(acc[0][j], fa0.x, fa1.x, fa0.y, fa1.y, fb.x, fb.y);
                            mma_fp16(acc[1][j], fa2.x, fa3.x, fa2.y, fa3.y, fb.x, fb.y);
                        }
                    }
                } else if (sec < 3) {
                    stage(sec + 1);
                }
                __syncthreads();
            }
        }

        // ---- dump gates to Cs (mma warps), then fused cell update (all) ----
        if (wid < 8) {
#pragma unroll
            for (int mt = 0; mt < 2; mt++) {
#pragma unroll
                for (int j = 0; j < 4; j++) {
                    const int row = mbase + mt * 16 + fr;
                    const int col = nbase + j * 8 + fc;
                    *(float2*)&Cs[row * 68 + col]       = make_float2(acc[mt][j][0], acc[mt][j][1]);
                    *(float2*)&Cs[(row + 8) * 68 + col] = make_float2(acc[mt][j][2], acc[mt][j][3]);
                }
            }
        }
        __syncthreads();

        {
            const float4 b4 = *(const float4*)&g_bias[colbase + hhi * 4];
#pragma unroll
            for (int r = 0; r < 4; r++) {
                const int row = rb4 + r;
                const int b   = bbase + row;
                float4 gv = *(const float4*)&Cs[row * 68 + hhi * 4];
                float iv = gv.x + b4.x;
                float fv = gv.y + b4.y;
                float gg = gv.z + b4.z;
                float ov = gv.w + b4.w;
                float co = c_in[b * H + hh];
                float cn = sigf(fv) * co + sigf(iv) * tanhf(gg);
                float hn = sigf(ov) * tanhf(cn);
                c_out[b * H + hh] = cn;
                h_out[b * H + hh] = hn;
            }
        }

        group_barrier(bt);   // h/c visible within group
        pp ^= 1;
    }
}

// ---------------- final FC ----------------
__global__ void __launch_bounds__(256) fc_kernel(const float* __restrict__ fc_w,
                                                 const float* __restrict__ fc_b,
                                                 float* __restrict__ out) {
    __shared__ float hs[H];
    const int b = blockIdx.x;
    const float* __restrict__ h_fin = g_h[0];
    for (int k = threadIdx.x; k < H; k += blockDim.x) hs[k] = h_fin[b * H + k];
    __syncthreads();
    const int w = threadIdx.x >> 5, lane = threadIdx.x & 31;
#pragma unroll
    for (int j = 0; j < 3; j++) {
        int o = w * 3 + j;
        float acc = 0.0f;
#pragma unroll 4
        for (int k = lane; k < H; k += 32)
            acc = fmaf(hs[k], fc_w[o * H + k], acc);
#pragma unroll
        for (int off = 16; off > 0; off >>= 1)
            acc += __shfl_xor_sync(0xffffffffu, acc, off);
        if (lane == 0) out[b * PRED + o] = acc + fc_b[o];
    }
}

// ---------------- launch ----------------
extern "C" void kernel_launch(void* const* d_in, const int* in_sizes, int n_in,
                              void* d_out, int out_size) {
    const float* x    = (const float*)d_in[0];
    const float* Wa   = (const float*)d_in[1];
    const float* Ua   = (const float*)d_in[2];
    const float* ba   = (const float*)d_in[3];
    const float* Va   = (const float*)d_in[4];
    const float* W_ih = (const float*)d_in[5];
    const float* W_hh = (const float*)d_in[6];
    const float* b_ih = (const float*)d_in[7];
    const float* b_hh = (const float*)d_in[8];
    const float* fc_w = (const float*)d_in[9];
    const float* fc_b = (const float*)d_in[10];
    float* out = (float*)d_out;

    cudaFuncSetAttribute(persist_kernel,
                         cudaFuncAttributeMaxDynamicSharedMemorySize, SMEM_TOTAL);

    init_kernel<<<512, 256>>>(W_ih, W_hh, b_ih, b_hh);
    xw_kernel<<<(BATCH * SEQ) / 32, 256>>>(x, Wa, ba);
    persist_kernel<<<NCTA, NTHR, SMEM_TOTAL>>>(x, Ua, Va);
    fc_kernel<<<BATCH, 256>>>(fc_w, fc_b, out);
}

// round 15
// speedup vs baseline: 1.4442x; 1.4442x over previous
#include <cuda_runtime.h>
#include <cuda_fp16.h>
#include <math.h>
#include <stdint.h>

#define BATCH 512
#define SEQ   256
#define D     64
#define H     512
#define G     2048
#define KDIM  576
#define PRED  24

#define NCTA  128
#define NTHR  256

// ---- smem layout (bytes). B first, then A region. ----
#define SWW    296                            /* words per A/B row (288 data + 8 pad) */
#define SM_B   0
#define SM_B_BYTES (64 * SWW * 4)             /* 75776  */
#define SM_A   SM_B_BYTES
#define SM_A_BYTES (128 * SWW * 4)            /* 151552 */
#define SMEM_TOTAL (SM_A + SM_A_BYTES)        /* 227328 */

// attn scratch offsets inside A region (barrier-separated from A-tile use)
#define AT_HC   0                             /* 4 x 1024 f32 = 16384 */
#define AT_PS   16384                         /* 4 x 4 x 64 f32 = 4096 */
#define AT_PRE  20480                         /* 4 x 64 f32 = 1024 */
#define AT_WRED 21504                         /* 16 f32 */

// ---------------- device scratch ----------------
__device__ __half  g_W16[KDIM * G];        // fp16 weights [k][g'], g' = hh*4+t
__device__ float   g_bias[G];
__device__ __half  g_h16[2][BATCH * H];    // hidden state, fp16 only
__device__ float   g_c[2][BATCH * H];      // cell state, fp32 (accumulates)
__device__ __half2 g_xatt16[BATCH * (D/2)];// attention-gated input, pair-packed
__device__ __half2 g_Ua16[(2*H/2) * D];    // Ua pair-packed: [pc][d], pc = k/2
__device__ float   g_xw[SEQ * BATCH * D];  // x@Wa + ba

// per-group (32-CTA) barriers, padded
__device__ unsigned g_gb_cnt[4][32];
__device__ volatile unsigned g_gb_gen[4][32];

__device__ __forceinline__ float sigf(float x) { return 1.0f / (1.0f + expf(-x)); }

// k-interleave: pair index pc (k/2) -> word within row
__device__ __forceinline__ int kword(int pc) {
    int grp = pc >> 3, cg = pc & 7;
    return grp * 8 + (cg & 3) * 2 + (cg >> 2);
}

__device__ __forceinline__ void mma_fp16(float* d, uint32_t a0, uint32_t a1,
                                         uint32_t a2, uint32_t a3,
                                         uint32_t b0, uint32_t b1) {
    asm volatile(
        "mma.sync.aligned.m16n8k16.row.col.f32.f16.f16.f32 "
        "{%0,%1,%2,%3}, {%4,%5,%6,%7}, {%8,%9}, {%0,%1,%2,%3};"
        : "+f"(d[0]), "+f"(d[1]), "+f"(d[2]), "+f"(d[3])
        : "r"(a0), "r"(a1), "r"(a2), "r"(a3), "r"(b0), "r"(b1));
}

// 32-CTA group barrier (group = blockIdx.x >> 5)
__device__ __forceinline__ void group_barrier(int grp) {
    __syncthreads();
    if (threadIdx.x == 0) {
        __threadfence();
        unsigned gen = g_gb_gen[grp][0];
        if (atomicAdd(&g_gb_cnt[grp][0], 1u) == 31u) {
            g_gb_cnt[grp][0] = 0;
            __threadfence();
            g_gb_gen[grp][0] = gen + 1;
        } else {
            while (g_gb_gen[grp][0] == gen) { }
        }
        __threadfence();
    }
    __syncthreads();
}

// ---------------- init ----------------
__global__ void __launch_bounds__(256) init_kernel(const float* __restrict__ W_ih,
                                                   const float* __restrict__ W_hh,
                                                   const float* __restrict__ b_ih,
                                                   const float* __restrict__ b_hh,
                                                   const float* __restrict__ Ua) {
    const int stride = gridDim.x * blockDim.x;
    const int tid0 = blockIdx.x * blockDim.x + threadIdx.x;
    for (int idx = tid0; idx < KDIM * G; idx += stride) {
        int k = idx / G, gp = idx - k * G;
        int hh = gp >> 2, t = gp & 3, g = t * H + hh;
        float v = (k < D) ? W_ih[g * D + k] : W_hh[g * H + (k - D)];
        g_W16[idx] = __float2half_rn(v);
    }
    for (int idx = tid0; idx < G; idx += stride) {
        int hh = idx >> 2, t = idx & 3, g = t * H + hh;
        g_bias[idx] = b_ih[g] + b_hh[g];
    }
    for (int idx = tid0; idx < (2 * H / 2) * D; idx += stride) {
        int pc = idx >> 6, d = idx & 63;
        g_Ua16[idx] = __floats2half2_rn(Ua[(2 * pc) * D + d], Ua[(2 * pc + 1) * D + d]);
    }
    for (int idx = tid0; idx < BATCH * H; idx += stride) {
        g_h16[0][idx] = __float2half_rn(0.0f);
        g_c[0][idx] = 0.0f;
    }
}

// ---------------- one-time xw = x@Wa + ba ----------------
__global__ void __launch_bounds__(256) xw_kernel(const float* __restrict__ x,
                                                 const float* __restrict__ Wa,
                                                 const float* __restrict__ ba) {
    __shared__ float Wa_s[D * D];
    __shared__ float xs[32][D];
    const int tid = threadIdx.x;
    const int r0 = blockIdx.x * 32;
    const int s = r0 / BATCH, b0 = r0 % BATCH;
    {
        const float4* src = (const float4*)Wa; float4* dst = (float4*)Wa_s;
#pragma unroll
        for (int j = 0; j < 4; j++) dst[tid + j * 256] = src[tid + j * 256];
    }
#pragma unroll
    for (int j = 0; j < 8; j++) {
        int idx = tid + j * 256; int i = idx >> 6, dd = idx & 63;
        xs[i][dd] = x[((b0 + i) * SEQ + s) * D + dd];
    }
    __syncthreads();
    const int d = tid & 63, grp = tid >> 6;
    float bv = ba[d], acc[8];
#pragma unroll
    for (int i = 0; i < 8; i++) acc[i] = bv;
#pragma unroll
    for (int k = 0; k < D; k += 4) {
        float w0 = Wa_s[k * D + d], w1 = Wa_s[(k + 1) * D + d];
        float w2 = Wa_s[(k + 2) * D + d], w3 = Wa_s[(k + 3) * D + d];
#pragma unroll
        for (int i = 0; i < 8; i++) {
            float4 xv = *(const float4*)&xs[grp * 8 + i][k];
            acc[i] = fmaf(xv.x, w0, acc[i]); acc[i] = fmaf(xv.y, w1, acc[i]);
            acc[i] = fmaf(xv.z, w2, acc[i]); acc[i] = fmaf(xv.w, w3, acc[i]);
        }
    }
#pragma unroll
    for (int i = 0; i < 8; i++) g_xw[(r0 + grp * 8 + i) * D + d] = acc[i];
}

// ---------------- persistent kernel ----------------
__global__ void __launch_bounds__(NTHR, 1)
persist_kernel(const float* __restrict__ x, const float* __restrict__ Va) {
    extern __shared__ __align__(16) char smem[];
    const int tid = threadIdx.x;
    const int cta = blockIdx.x;
    const int ct = cta & 31, bt = cta >> 5;
    const int colbase = ct * 64, bbase = bt * 128;
    const int lane = tid & 31, wid = tid >> 5;

    // ---- load fp16 weight slice into interleaved B smem (once) ----
    {
        __half* Bh = (__half*)(smem + SM_B);
        for (int idx = tid; idx < 64 * KDIM; idx += NTHR) {
            int k = idx >> 6, n = idx & 63;
            __half w = g_W16[k * G + colbase + n];
            Bh[n * (SWW * 2) + kword(k >> 1) * 2 + (k & 1)] = w;
        }
    }

    // attn scratch views (overlay A region)
    float (*hc_s)[2 * H] = (float (*)[2 * H])(smem + SM_A + AT_HC);
    float* ps    = (float*)(smem + SM_A + AT_PS);     // [ks][row][ad]
    float* pre_s = (float*)(smem + SM_A + AT_PRE);
    float* wred  = (float*)(smem + SM_A + AT_WRED);
    float* wred2 = wred + 8;
    float* Cs    = (float*)(smem + SM_A);             // epilogue scratch 128x68

    // attn mapping: ks = k-quarter 0..3, ad = feature 0..63
    const int ks = tid >> 6, ad = tid & 63;
    const int kbase = ks * 256;

    // mma mapping: 8 warps = 4 row-groups x 2 col-groups
    const int mbase = (wid & 3) * 32;
    const int nbase = (wid >> 2) * 32;
    const int fr = lane >> 2;
    const int fc = (lane & 3) * 2;

    // cell-update mapping
    const int hhi   = tid & 15;
    const int rbase = (tid >> 4) * 8;
    const int hh    = (colbase >> 2) + hhi;

    int pp = 0;
    group_barrier(bt);

    for (int s = 0; s < SEQ; s++) {
        const __half* __restrict__ h_in = g_h16[pp];
        const float*  __restrict__ c_in = g_c[pp];
        __half* __restrict__ h_out = g_h16[1 - pp];
        float*  __restrict__ c_out = g_c[1 - pp];

        // ===================== attn phase =====================
        {
            // stage hc (fp32 in smem): h fp16->f32, c fp32
#pragma unroll
            for (int j = 0; j < 4; j++) {                 // 1024 uint32 of h16
                int idx = tid + j * 256;
                int r = idx >> 8, k2 = idx & 255;
                uint32_t u = ((const uint32_t*)(h_in + (cta * 4 + r) * H))[k2];
                float2 f = __half22float2(*(const __half2*)&u);
                *(float2*)&hc_s[r][k2 * 2] = f;
            }
#pragma unroll
            for (int j = 0; j < 2; j++) {                 // 512 float4 of c
                int idx = tid + j * 256;
                int r = idx >> 7, q = idx & 127;
                float4 v = *(const float4*)(c_in + (cta * 4 + r) * H + q * 4);
                *(float4*)&hc_s[r][H + q * 4] = v;
            }
            __syncthreads();

            // each thread: its k-quarter, all 4 rows; Ua direct LDG (half2-packed)
            float a0 = 0.0f, a1 = 0.0f, a2 = 0.0f, a3 = 0.0f;
            {
                const __half2* Up = g_Ua16 + (kbase >> 1) * D + ad;
#pragma unroll 8
                for (int kk = 0; kk < 256; kk += 4) {
                    float2 f0 = __half22float2(Up[(kk >> 1) * D]);
                    float2 f1 = __half22float2(Up[((kk >> 1) + 1) * D]);
                    float4 h0 = *(const float4*)&hc_s[0][kbase + kk];
                    float4 h1 = *(const float4*)&hc_s[1][kbase + kk];
                    float4 h2 = *(const float4*)&hc_s[2][kbase + kk];
                    float4 h3 = *(const float4*)&hc_s[3][kbase + kk];
                    a0 = fmaf(h0.x, f0.x, a0); a0 = fmaf(h0.y, f0.y, a0);
                    a0 = fmaf(h0.z, f1.x, a0); a0 = fmaf(h0.w, f1.y, a0);
                    a1 = fmaf(h1.x, f0.x, a1); a1 = fmaf(h1.y, f0.y, a1);
                    a1 = fmaf(h1.z, f1.x, a1); a1 = fmaf(h1.w, f1.y, a1);
                    a2 = fmaf(h2.x, f0.x, a2); a2 = fmaf(h2.y, f0.y, a2);
                    a2 = fmaf(h2.z, f1.x, a2); a2 = fmaf(h2.w, f1.y, a2);
                    a3 = fmaf(h3.x, f0.x, a3); a3 = fmaf(h3.y, f0.y, a3);
                    a3 = fmaf(h3.z, f1.x, a3); a3 = fmaf(h3.w, f1.y, a3);
                }
            }
            ps[ks * 256 + 0 * 64 + ad] = a0;
            ps[ks * 256 + 1 * 64 + ad] = a1;
            ps[ks * 256 + 2 * 64 + ad] = a2;
            ps[ks * 256 + 3 * 64 + ad] = a3;
            __syncthreads();

            // combine + tanh  (row = tid>>6 now)
            const int r = ks;          // reuse: tid>>6 as row
            const int ab = cta * 4 + r;
            {
                float sum = ps[0 * 256 + r * 64 + ad] + ps[1 * 256 + r * 64 + ad] +
                            ps[2 * 256 + r * 64 + ad] + ps[3 * 256 + r * 64 + ad] +
                            g_xw[(s * BATCH + ab) * D + ad];
                pre_s[r * D + ad] = tanhf(sum);
            }
            __syncthreads();

            // a = pre @ Va  (Va direct LDG, coalesced)
            float v0 = 0.0f, v1 = 0.0f, v2 = 0.0f, v3 = 0.0f;
#pragma unroll 4
            for (int k = 0; k < D; k += 4) {
                float4 pr = *(const float4*)&pre_s[r * D + k];
                v0 = fmaf(pr.x, Va[(k + 0) * D + ad], v0);
                v1 = fmaf(pr.y, Va[(k + 1) * D + ad], v1);
                v2 = fmaf(pr.z, Va[(k + 2) * D + ad], v2);
                v3 = fmaf(pr.w, Va[(k + 3) * D + ad], v3);
            }
            float av = (v0 + v1) + (v2 + v3);

            // softmax over 64 lanes (2 warps per row)
            float m = av;
#pragma unroll
            for (int off = 16; off > 0; off >>= 1)
                m = fmaxf(m, __shfl_xor_sync(0xffffffffu, m, off));
            if (lane == 0) wred[wid] = m;
            __syncthreads();
            m = fmaxf(wred[r * 2], wred[r * 2 + 1]);

            float e = expf(av - m);
            float ssum = e;
#pragma unroll
            for (int off = 16; off > 0; off >>= 1)
                ssum += __shfl_xor_sync(0xffffffffu, ssum, off);
            if (lane == 0) wred2[wid] = ssum;
            __syncthreads();
            ssum = wred2[r * 2] + wred2[r * 2 + 1];

            float xa = (e / ssum) * x[(ab * SEQ + s) * D + ad];
            // pack pairs via shfl, even-ad lanes store half2
            float xo = __shfl_down_sync(0xffffffffu, xa, 1);
            if ((ad & 1) == 0)
                g_xatt16[ab * (D / 2) + (ad >> 1)] = __floats2half2_rn(xa, xo);
        }

        group_barrier(bt);   // xatt visible within group

        // ========== stage A tile (fp16 pairs, no cvt): 128 rows x 72 uint4 ==========
        {
            uint32_t* Aw = (uint32_t*)(smem + SM_A);
#pragma unroll 4
            for (int j = 0; j < 36; j++) {
                int idx = tid + j * 256;          // 0..9215
                int row = idx / 72;
                int q   = idx - row * 72;         // uint4 index within row (8 halves each)
                uint4 v;
                if (q < 8)
                    v = *(const uint4*)((const char*)(g_xatt16 + (bbase + row) * (D / 2)) + q * 16);
                else
                    v = *(const uint4*)((const char*)(h_in + (bbase + row) * H) + (q - 8) * 16);
                uint32_t* Ar = Aw + row * SWW;
                int pc = q * 4;
                Ar[kword(pc + 0)] = v.x;
                Ar[kword(pc + 1)] = v.y;
                Ar[kword(pc + 2)] = v.z;
                Ar[kword(pc + 3)] = v.w;
            }
        }
        __syncthreads();

        // ===================== mma mainloop =====================
        float acc[2][4][4];
#pragma unroll
        for (int mt = 0; mt < 2; mt++)
#pragma unroll
            for (int j = 0; j < 4; j++)
#pragma unroll
                for (int q = 0; q < 4; q++) acc[mt][j][q] = 0.0f;

        {
            const uint32_t* Aw = (const uint32_t*)(smem + SM_A);
            const uint32_t* Bw = (const uint32_t*)(smem + SM_B);
#pragma unroll 2
            for (int kst = 0; kst < 36; kst++) {
                const int kw = kst * 8 + fc;
                uint2 fa0 = *(const uint2*)&Aw[(mbase + fr) * SWW + kw];
                uint2 fa1 = *(const uint2*)&Aw[(mbase + fr + 8) * SWW + kw];
                uint2 fa2 = *(const uint2*)&Aw[(mbase + 16 + fr) * SWW + kw];
                uint2 fa3 = *(const uint2*)&Aw[(mbase + 24 + fr) * SWW + kw];
#pragma unroll
                for (int j = 0; j < 4; j++) {
                    uint2 fb = *(const uint2*)&Bw[(nbase + j * 8 + fr) * SWW + kw];
                    mma_fp16(acc[0][j], fa0.x, fa1.x, fa0.y, fa1.y, fb.x, fb.y);
                    mma_fp16(acc[1][j], fa2.x, fa3.x, fa2.y, fa3.y, fb.x, fb.y);
                }
            }
        }
        __syncthreads();   // all warps done reading A before Cs overwrite

        // ---- dump gates to Cs, then fused cell update ----
#pragma unroll
        for (int mt = 0; mt < 2; mt++) {
#pragma unroll
            for (int j = 0; j < 4; j++) {
                const int row = mbase + mt * 16 + fr;
                const int col = nbase + j * 8 + fc;
                *(float2*)&Cs[row * 68 + col]       = make_float2(acc[mt][j][0], acc[mt][j][1]);
                *(float2*)&Cs[(row + 8) * 68 + col] = make_float2(acc[mt][j][2], acc[mt][j][3]);
            }
        }
        __syncthreads();

        {
            const float4 b4 = *(const float4*)&g_bias[colbase + hhi * 4];
#pragma unroll
            for (int rr = 0; rr < 8; rr++) {
                const int row = rbase + rr;
                const int b   = bbase + row;
                float4 gv = *(const float4*)&Cs[row * 68 + hhi * 4];
                float iv = gv.x + b4.x;
                float fv = gv.y + b4.y;
                float gg = gv.z + b4.z;
                float ov = gv.w + b4.w;
                float co = c_in[b * H + hh];
                float cn = sigf(fv) * co + sigf(iv) * tanhf(gg);
                float hn = sigf(ov) * tanhf(cn);
                c_out[b * H + hh] = cn;
                h_out[b * H + hh] = __float2half_rn(hn);
            }
        }

        group_barrier(bt);   // h/c visible within group
        pp ^= 1;
    }
}

// ---------------- final FC ----------------
__global__ void __launch_bounds__(256) fc_kernel(const float* __restrict__ fc_w,
                                                 const float* __restrict__ fc_b,
                                                 float* __restrict__ out) {
    __shared__ float hs[H];
    const int b = blockIdx.x;
    const __half* __restrict__ h_fin = g_h16[0];   // SEQ even -> final in buf 0
    for (int k = threadIdx.x; k < H; k += blockDim.x)
        hs[k] = __half2float(h_fin[b * H + k]);
    __syncthreads();
    const int w = threadIdx.x >> 5, lane = threadIdx.x & 31;
#pragma unroll
    for (int j = 0; j < 3; j++) {
        int o = w * 3 + j;
        float acc = 0.0f;
#pragma unroll 4
        for (int k = lane; k < H; k += 32)
            acc = fmaf(hs[k], fc_w[o * H + k], acc);
#pragma unroll
        for (int off = 16; off > 0; off >>= 1)
            acc += __shfl_xor_sync(0xffffffffu, acc, off);
        if (lane == 0) out[b * PRED + o] = acc + fc_b[o];
    }
}

// ---------------- launch ----------------
extern "C" void kernel_launch(void* const* d_in, const int* in_sizes, int n_in,
                              void* d_out, int out_size) {
    const float* x    = (const float*)d_in[0];
    const float* Wa   = (const float*)d_in[1];
    const float* Ua   = (const float*)d_in[2];
    const float* ba   = (const float*)d_in[3];
    const float* Va   = (const float*)d_in[4];
    const float* W_ih = (const float*)d_in[5];
    const float* W_hh = (const float*)d_in[6];
    const float* b_ih = (const float*)d_in[7];
    const float* b_hh = (const float*)d_in[8];
    const float* fc_w = (const float*)d_in[9];
    const float* fc_b = (const float*)d_in[10];
    float* out = (float*)d_out;

    cudaFuncSetAttribute(persist_kernel,
                         cudaFuncAttributeMaxDynamicSharedMemorySize, SMEM_TOTAL);

    init_kernel<<<512, 256>>>(W_ih, W_hh, b_ih, b_hh, Ua);
    xw_kernel<<<(BATCH * SEQ) / 32, 256>>>(x, Wa, ba);
    persist_kernel<<<NCTA, NTHR, SMEM_TOTAL>>>(x, Va);
    fc_kernel<<<BATCH, 256>>>(fc_w, fc_b, out);
}

// round 17
// speedup vs baseline: 1.5208x; 1.0531x over previous
#include <cuda_runtime.h>
#include <cuda_fp16.h>
#include <math.h>
#include <stdint.h>

#define BATCH 512
#define SEQ   256
#define D     64
#define H     512
#define G     2048
#define KDIM  576
#define PRED  24

#define NCTA  128
#define NTHR  256

// ---- smem layout (bytes). B first, then A region. ----
#define SWW    296                            /* words per A/B row (288 data + 8 pad) */
#define SM_B   0
#define SM_B_BYTES (64 * SWW * 4)             /* 75776  */
#define SM_A   SM_B_BYTES
#define SM_A_BYTES (128 * SWW * 4)            /* 151552 */
#define SMEM_TOTAL (SM_A + SM_A_BYTES)        /* 227328 */

// attn scratch offsets inside A region (barrier-separated from A-tile use)
#define AT_HC   0                             /* 4 x 1024 f32 = 16384 */
#define AT_PS   16384                         /* 4 x 4 x 64 f32 = 4096 */
#define AT_PRE  20480                         /* 4 x 64 f32 = 1024 */
#define AT_WRED 21504                         /* 16 f32 */

// ---------------- device scratch ----------------
__device__ __half  g_W16[KDIM * G];        // fp16 weights [k][g'], g' = hh*4+t
__device__ float   g_bias[G];
__device__ __half  g_h16[2][BATCH * H];    // hidden state, fp16 only
__device__ float   g_c[2][BATCH * H];      // cell state, fp32 (accumulates)
__device__ __half2 g_xatt16[BATCH * (D/2)];// attention-gated input, pair-packed
__device__ __half2 g_Ua16[(2*H/2) * D];    // Ua pair-packed: [pc][d], pc = k/2
__device__ float   g_xw[SEQ * BATCH * D];  // x@Wa + ba

// per-group (32-CTA) barriers, padded
__device__ unsigned g_gb_cnt[4][32];
__device__ volatile unsigned g_gb_gen[4][32];

__device__ __forceinline__ float sigf(float x) { return 1.0f / (1.0f + expf(-x)); }

// k-interleave: pair index pc (k/2) -> word within row
__device__ __forceinline__ int kword(int pc) {
    int grp = pc >> 3, cg = pc & 7;
    return grp * 8 + (cg & 3) * 2 + (cg >> 2);
}

__device__ __forceinline__ void mma_fp16(float* d, uint32_t a0, uint32_t a1,
                                         uint32_t a2, uint32_t a3,
                                         uint32_t b0, uint32_t b1) {
    asm volatile(
        "mma.sync.aligned.m16n8k16.row.col.f32.f16.f16.f32 "
        "{%0,%1,%2,%3}, {%4,%5,%6,%7}, {%8,%9}, {%0,%1,%2,%3};"
        : "+f"(d[0]), "+f"(d[1]), "+f"(d[2]), "+f"(d[3])
        : "r"(a0), "r"(a1), "r"(a2), "r"(a3), "r"(b0), "r"(b1));
}

// 32-CTA group barrier (group = blockIdx.x >> 5)
__device__ __forceinline__ void group_barrier(int grp) {
    __syncthreads();
    if (threadIdx.x == 0) {
        __threadfence();
        unsigned gen = g_gb_gen[grp][0];
        if (atomicAdd(&g_gb_cnt[grp][0], 1u) == 31u) {
            g_gb_cnt[grp][0] = 0;
            __threadfence();
            g_gb_gen[grp][0] = gen + 1;
        } else {
            while (g_gb_gen[grp][0] == gen) { }
        }
        __threadfence();
    }
    __syncthreads();
}

// ---------------- init ----------------
__global__ void __launch_bounds__(256) init_kernel(const float* __restrict__ W_ih,
                                                   const float* __restrict__ W_hh,
                                                   const float* __restrict__ b_ih,
                                                   const float* __restrict__ b_hh,
                                                   const float* __restrict__ Ua) {
    const int stride = gridDim.x * blockDim.x;
    const int tid0 = blockIdx.x * blockDim.x + threadIdx.x;
    for (int idx = tid0; idx < KDIM * G; idx += stride) {
        int k = idx / G, gp = idx - k * G;
        int hh = gp >> 2, t = gp & 3, g = t * H + hh;
        float v = (k < D) ? W_ih[g * D + k] : W_hh[g * H + (k - D)];
        g_W16[idx] = __float2half_rn(v);
    }
    for (int idx = tid0; idx < G; idx += stride) {
        int hh = idx >> 2, t = idx & 3, g = t * H + hh;
        g_bias[idx] = b_ih[g] + b_hh[g];
    }
    for (int idx = tid0; idx < (2 * H / 2) * D; idx += stride) {
        int pc = idx >> 6, d = idx & 63;
        g_Ua16[idx] = __floats2half2_rn(Ua[(2 * pc) * D + d], Ua[(2 * pc + 1) * D + d]);
    }
    for (int idx = tid0; idx < BATCH * H; idx += stride) {
        g_h16[0][idx] = __float2half_rn(0.0f);
        g_c[0][idx] = 0.0f;
    }
}

// ---------------- one-time xw = x@Wa + ba ----------------
__global__ void __launch_bounds__(256) xw_kernel(const float* __restrict__ x,
                                                 const float* __restrict__ Wa,
                                                 const float* __restrict__ ba) {
    __shared__ float Wa_s[D * D];
    __shared__ float xs[32][D];
    const int tid = threadIdx.x;
    const int r0 = blockIdx.x * 32;
    const int s = r0 / BATCH, b0 = r0 % BATCH;
    {
        const float4* src = (const float4*)Wa; float4* dst = (float4*)Wa_s;
#pragma unroll
        for (int j = 0; j < 4; j++) dst[tid + j * 256] = src[tid + j * 256];
    }
#pragma unroll
    for (int j = 0; j < 8; j++) {
        int idx = tid + j * 256; int i = idx >> 6, dd = idx & 63;
        xs[i][dd] = x[((b0 + i) * SEQ + s) * D + dd];
    }
    __syncthreads();
    const int d = tid & 63, grp = tid >> 6;
    float bv = ba[d], acc[8];
#pragma unroll
    for (int i = 0; i < 8; i++) acc[i] = bv;
#pragma unroll
    for (int k = 0; k < D; k += 4) {
        float w0 = Wa_s[k * D + d], w1 = Wa_s[(k + 1) * D + d];
        float w2 = Wa_s[(k + 2) * D + d], w3 = Wa_s[(k + 3) * D + d];
#pragma unroll
        for (int i = 0; i < 8; i++) {
            float4 xv = *(const float4*)&xs[grp * 8 + i][k];
            acc[i] = fmaf(xv.x, w0, acc[i]); acc[i] = fmaf(xv.y, w1, acc[i]);
            acc[i] = fmaf(xv.z, w2, acc[i]); acc[i] = fmaf(xv.w, w3, acc[i]);
        }
    }
#pragma unroll
    for (int i = 0; i < 8; i++) g_xw[(r0 + grp * 8 + i) * D + d] = acc[i];
}

// ---------------- persistent kernel ----------------
__global__ void __launch_bounds__(NTHR, 1)
persist_kernel(const float* __restrict__ x, const float* __restrict__ Va) {
    extern __shared__ __align__(16) char smem[];
    const int tid = threadIdx.x;
    const int cta = blockIdx.x;
    const int ct = cta & 31, bt = cta >> 5;
    const int colbase = ct * 64, bbase = bt * 128;
    const int lane = tid & 31, wid = tid >> 5;

    // ---- load fp16 weight slice into interleaved B smem (once) ----
    {
        __half* Bh = (__half*)(smem + SM_B);
        for (int idx = tid; idx < 64 * KDIM; idx += NTHR) {
            int k = idx >> 6, n = idx & 63;
            __half w = g_W16[k * G + colbase + n];
            Bh[n * (SWW * 2) + kword(k >> 1) * 2 + (k & 1)] = w;
        }
    }

    // attn scratch views (overlay A region)
    float (*hc_s)[2 * H] = (float (*)[2 * H])(smem + SM_A + AT_HC);
    float* ps    = (float*)(smem + SM_A + AT_PS);     // [ks][row][ad]
    float* pre_s = (float*)(smem + SM_A + AT_PRE);
    float* wred  = (float*)(smem + SM_A + AT_WRED);
    float* wred2 = wred + 8;
    float* Cs    = (float*)(smem + SM_A);             // epilogue scratch 128x68

    // attn mapping: ks = k-quarter 0..3, ad = feature 0..63
    const int ks = tid >> 6, ad = tid & 63;
    const int kbase = ks * 256;

    // mma mapping: 8 warps = 4 row-groups x 2 col-groups
    const int mbase = (wid & 3) * 32;
    const int nbase = (wid >> 2) * 32;
    const int fr = lane >> 2;
    const int fc = (lane & 3) * 2;

    // cell-update mapping
    const int hhi   = tid & 15;
    const int rbase = (tid >> 4) * 8;
    const int hh    = (colbase >> 2) + hhi;

    int pp = 0;
    group_barrier(bt);

    for (int s = 0; s < SEQ; s++) {
        const __half* __restrict__ h_in = g_h16[pp];
        const float*  __restrict__ c_in = g_c[pp];
        __half* __restrict__ h_out = g_h16[1 - pp];
        float*  __restrict__ c_out = g_c[1 - pp];

        // ===================== attn phase =====================
        {
            // stage hc (fp32 in smem): h fp16->f32, c fp32
#pragma unroll
            for (int j = 0; j < 4; j++) {                 // 1024 uint32 of h16
                int idx = tid + j * 256;
                int r = idx >> 8, k2 = idx & 255;
                uint32_t u = ((const uint32_t*)(h_in + (cta * 4 + r) * H))[k2];
                float2 f = __half22float2(*(const __half2*)&u);
                *(float2*)&hc_s[r][k2 * 2] = f;
            }
#pragma unroll
            for (int j = 0; j < 2; j++) {                 // 512 float4 of c
                int idx = tid + j * 256;
                int r = idx >> 7, q = idx & 127;
                float4 v = *(const float4*)(c_in + (cta * 4 + r) * H + q * 4);
                *(float4*)&hc_s[r][H + q * 4] = v;
            }
            __syncthreads();

            // each thread: its k-quarter, all 4 rows; Ua direct LDG (half2-packed)
            float a0 = 0.0f, a1 = 0.0f, a2 = 0.0f, a3 = 0.0f;
            {
                const __half2* Up = g_Ua16 + (kbase >> 1) * D + ad;
#pragma unroll 8
                for (int kk = 0; kk < 256; kk += 4) {
                    float2 f0 = __half22float2(Up[(kk >> 1) * D]);
                    float2 f1 = __half22float2(Up[((kk >> 1) + 1) * D]);
                    float4 h0 = *(const float4*)&hc_s[0][kbase + kk];
                    float4 h1 = *(const float4*)&hc_s[1][kbase + kk];
                    float4 h2 = *(const float4*)&hc_s[2][kbase + kk];
                    float4 h3 = *(const float4*)&hc_s[3][kbase + kk];
                    a0 = fmaf(h0.x, f0.x, a0); a0 = fmaf(h0.y, f0.y, a0);
                    a0 = fmaf(h0.z, f1.x, a0); a0 = fmaf(h0.w, f1.y, a0);
                    a1 = fmaf(h1.x, f0.x, a1); a1 = fmaf(h1.y, f0.y, a1);
                    a1 = fmaf(h1.z, f1.x, a1); a1 = fmaf(h1.w, f1.y, a1);
                    a2 = fmaf(h2.x, f0.x, a2); a2 = fmaf(h2.y, f0.y, a2);
                    a2 = fmaf(h2.z, f1.x, a2); a2 = fmaf(h2.w, f1.y, a2);
                    a3 = fmaf(h3.x, f0.x, a3); a3 = fmaf(h3.y, f0.y, a3);
                    a3 = fmaf(h3.z, f1.x, a3); a3 = fmaf(h3.w, f1.y, a3);
                }
            }
            ps[ks * 256 + 0 * 64 + ad] = a0;
            ps[ks * 256 + 1 * 64 + ad] = a1;
            ps[ks * 256 + 2 * 64 + ad] = a2;
            ps[ks * 256 + 3 * 64 + ad] = a3;
            __syncthreads();

            // combine + tanh  (row = tid>>6 now)
            const int r = ks;
            const int ab = cta * 4 + r;
            {
                float sum = ps[0 * 256 + r * 64 + ad] + ps[1 * 256 + r * 64 + ad] +
                            ps[2 * 256 + r * 64 + ad] + ps[3 * 256 + r * 64 + ad] +
                            g_xw[(s * BATCH + ab) * D + ad];
                pre_s[r * D + ad] = tanhf(sum);
            }
            __syncthreads();

            // a = pre @ Va  (Va direct LDG, coalesced)
            float v0 = 0.0f, v1 = 0.0f, v2 = 0.0f, v3 = 0.0f;
#pragma unroll 4
            for (int k = 0; k < D; k += 4) {
                float4 pr = *(const float4*)&pre_s[r * D + k];
                v0 = fmaf(pr.x, Va[(k + 0) * D + ad], v0);
                v1 = fmaf(pr.y, Va[(k + 1) * D + ad], v1);
                v2 = fmaf(pr.z, Va[(k + 2) * D + ad], v2);
                v3 = fmaf(pr.w, Va[(k + 3) * D + ad], v3);
            }
            float av = (v0 + v1) + (v2 + v3);

            // softmax over 64 lanes (2 warps per row)
            float m = av;
#pragma unroll
            for (int off = 16; off > 0; off >>= 1)
                m = fmaxf(m, __shfl_xor_sync(0xffffffffu, m, off));
            if (lane == 0) wred[wid] = m;
            __syncthreads();
            m = fmaxf(wred[r * 2], wred[r * 2 + 1]);

            float e = expf(av - m);
            float ssum = e;
#pragma unroll
            for (int off = 16; off > 0; off >>= 1)
                ssum += __shfl_xor_sync(0xffffffffu, ssum, off);
            if (lane == 0) wred2[wid] = ssum;
            __syncthreads();
            ssum = wred2[r * 2] + wred2[r * 2 + 1];

            float xa = (e / ssum) * x[(ab * SEQ + s) * D + ad];
            float xo = __shfl_down_sync(0xffffffffu, xa, 1);
            if ((ad & 1) == 0)
                g_xatt16[ab * (D / 2) + (ad >> 1)] = __floats2half2_rn(xa, xo);
        }

        group_barrier(bt);   // xatt visible within group

        // ========== gates: 6-section pipelined A-stage + mma ==========
        float acc[2][4][4];
#pragma unroll
        for (int mt = 0; mt < 2; mt++)
#pragma unroll
            for (int j = 0; j < 4; j++)
#pragma unroll
                for (int q = 0; q < 4; q++) acc[mt][j][q] = 0.0f;

        {
            uint32_t* Aw = (uint32_t*)(smem + SM_A);
            const uint32_t* Bw = (const uint32_t*)(smem + SM_B);
            uint4 v[6];

            // prologue: load + store section 0 (q 0..11: xatt for q<8, else h)
#pragma unroll
            for (int i = 0; i < 6; i++) {
                int idx = tid + i * 256;          // 0..1535
                int row = idx / 12, q = idx - row * 12;
                v[i] = (q < 8)
                    ? *(const uint4*)((const char*)(g_xatt16 + (bbase + row) * (D / 2)) + q * 16)
                    : *(const uint4*)((const char*)(h_in + (bbase + row) * H) + (q - 8) * 16);
            }
#pragma unroll
            for (int i = 0; i < 6; i++) {
                int idx = tid + i * 256;
                int row = idx / 12, q = idx - row * 12;
                uint32_t* Ar = Aw + row * SWW;
                int pc = q * 4;
                Ar[kword(pc + 0)] = v[i].x; Ar[kword(pc + 1)] = v[i].y;
                Ar[kword(pc + 2)] = v[i].z; Ar[kword(pc + 3)] = v[i].w;
            }
            __syncthreads();

#pragma unroll
            for (int sec = 0; sec < 6; sec++) {
                // issue next section's loads (latency hides under mma below)
                if (sec < 5) {
#pragma unroll
                    for (int i = 0; i < 6; i++) {
                        int idx = tid + i * 256;
                        int row = idx / 12, qq = idx - row * 12;
                        int q = (sec + 1) * 12 + qq;   // >= 12: always h
                        v[i] = *(const uint4*)((const char*)(h_in + (bbase + row) * H) + (q - 8) * 16);
                    }
                }
                // mma over this section's 6 kst
#pragma unroll
                for (int ki = 0; ki < 6; ki++) {
                    const int kw = (sec * 6 + ki) * 8 + fc;
                    uint2 fa0 = *(const uint2*)&Aw[(mbase + fr) * SWW + kw];
                    uint2 fa1 = *(const uint2*)&Aw[(mbase + fr + 8) * SWW + kw];
                    uint2 fa2 = *(const uint2*)&Aw[(mbase + 16 + fr) * SWW + kw];
                    uint2 fa3 = *(const uint2*)&Aw[(mbase + 24 + fr) * SWW + kw];
#pragma unroll
                    for (int j = 0; j < 4; j++) {
                        uint2 fb = *(const uint2*)&Bw[(nbase + j * 8 + fr) * SWW + kw];
                        mma_fp16(acc[0][j], fa0.x, fa1.x, fa0.y, fa1.y, fb.x, fb.y);
                        mma_fp16(acc[1][j], fa2.x, fa3.x, fa2.y, fa3.y, fb.x, fb.y);
                    }
                }
                // store next section (disjoint words from current mma reads)
                if (sec < 5) {
#pragma unroll
                    for (int i = 0; i < 6; i++) {
                        int idx = tid + i * 256;
                        int row = idx / 12, qq = idx - row * 12;
                        int pc = ((sec + 1) * 12 + qq) * 4;
                        uint32_t* Ar = Aw + row * SWW;
                        Ar[kword(pc + 0)] = v[i].x; Ar[kword(pc + 1)] = v[i].y;
                        Ar[kword(pc + 2)] = v[i].z; Ar[kword(pc + 3)] = v[i].w;
                    }
                    __syncthreads();
                }
            }
        }
        __syncthreads();   // all warps done reading A before Cs overwrite

        // ---- dump gates to Cs, then fused cell update ----
#pragma unroll
        for (int mt = 0; mt < 2; mt++) {
#pragma unroll
            for (int j = 0; j < 4; j++) {
                const int row = mbase + mt * 16 + fr;
                const int col = nbase + j * 8 + fc;
                *(float2*)&Cs[row * 68 + col]       = make_float2(acc[mt][j][0], acc[mt][j][1]);
                *(float2*)&Cs[(row + 8) * 68 + col] = make_float2(acc[mt][j][2], acc[mt][j][3]);
            }
        }
        __syncthreads();

        {
            const float4 b4 = *(const float4*)&g_bias[colbase + hhi * 4];
#pragma unroll
            for (int rr = 0; rr < 8; rr++) {
                const int row = rbase + rr;
                const int b   = bbase + row;
                float4 gv = *(const float4*)&Cs[row * 68 + hhi * 4];
                float iv = gv.x + b4.x;
                float fv = gv.y + b4.y;
                float gg = gv.z + b4.z;
                float ov = gv.w + b4.w;
                float co = c_in[b * H + hh];
                float cn = sigf(fv) * co + sigf(iv) * tanhf(gg);
                float hn = sigf(ov) * tanhf(cn);
                c_out[b * H + hh] = cn;
                h_out[b * H + hh] = __float2half_rn(hn);
            }
        }

        group_barrier(bt);   // h/c visible within group
        pp ^= 1;
    }
}

// ---------------- final FC ----------------
__global__ void __launch_bounds__(256) fc_kernel(const float* __restrict__ fc_w,
                                                 const float* __restrict__ fc_b,
                                                 float* __restrict__ out) {
    __shared__ float hs[H];
    const int b = blockIdx.x;
    const __half* __restrict__ h_fin = g_h16[0];   // SEQ even -> final in buf 0
    for (int k = threadIdx.x; k < H; k += blockDim.x)
        hs[k] = __half2float(h_fin[b * H + k]);
    __syncthreads();
    const int w = threadIdx.x >> 5, lane = threadIdx.x & 31;
#pragma unroll
    for (int j = 0; j < 3; j++) {
        int o = w * 3 + j;
        float acc = 0.0f;
#pragma unroll 4
        for (int k = lane; k < H; k += 32)
            acc = fmaf(hs[k], fc_w[o * H + k], acc);
#pragma unroll
        for (int off = 16; off > 0; off >>= 1)
            acc += __shfl_xor_sync(0xffffffffu, acc, off);
        if (lane == 0) out[b * PRED + o] = acc + fc_b[o];
    }
}

// ---------------- launch ----------------
extern "C" void kernel_launch(void* const* d_in, const int* in_sizes, int n_in,
                              void* d_out, int out_size) {
    const float* x    = (const float*)d_in[0];
    const float* Wa   = (const float*)d_in[1];
    const float* Ua   = (const float*)d_in[2];
    const float* ba   = (const float*)d_in[3];
    const float* Va   = (const float*)d_in[4];
    const float* W_ih = (const float*)d_in[5];
    const float* W_hh = (const float*)d_in[6];
    const float* b_ih = (const float*)d_in[7];
    const float* b_hh = (const float*)d_in[8];
    const float* fc_w = (const float*)d_in[9];
    const float* fc_b = (const float*)d_in[10];
    float* out = (float*)d_out;

    cudaFuncSetAttribute(persist_kernel,
                         cudaFuncAttributeMaxDynamicSharedMemorySize, SMEM_TOTAL);

    init_kernel<<<512, 256>>>(W_ih, W_hh, b_ih, b_hh, Ua);
    xw_kernel<<<(BATCH * SEQ) / 32, 256>>>(x, Wa, ba);
    persist_kernel<<<NCTA, NTHR, SMEM_TOTAL>>>(x, Va);
    fc_kernel<<<BATCH, 256>>>(fc_w, fc_b, out);
}